// round 6
// baseline (speedup 1.0000x reference)
#include <cuda_runtime.h>
#include <cuda_bf16.h>
#include <cstdint>

// ---------------------------------------------------------------------------
// Pipeline:
//   S : split x -> bf16 hi/lo             -> g_Ah/g_Al [M,192] (cols 0..127)
//   P1: split W11 (hi|hi|lo)              -> g_B11 [128,384] bf16
//   P2: fold plane-stress D into W12, split -> g_Bp [384,576] bf16
//   A : fc11 mma.sync split GEMM + dnew   -> g_dnew  [M,64]
//   B : prefix-max over T -> dmg, bf16 split -> g_Ah/g_Al cols 128..191
//   C : fc12 mma.sync split GEMM (K'=576) + seq epilogue
//        -> g_strain (= sig_tr) [M,384], g_seq [M,128]
//   E : J2 plasticity scan                -> g_scale [M,128]
//   F : fc2 + softplus                    -> out
// Round-6 change: barrier-free GEMM mainloops. B operand smem-resident
// (loaded once), A streamed straight from global into mma fragments.
// ---------------------------------------------------------------------------

typedef unsigned long long u64;

#define MM 131072   // 256*512

__device__ __align__(16) float g_dnew[(size_t)MM * 64];
__device__ __align__(16) float g_strain[(size_t)MM * 384];
__device__ __align__(16) float g_seq[(size_t)MM * 128];
__device__ __align__(16) float g_scale[(size_t)MM * 128];
__device__ __align__(16) __nv_bfloat16 g_Ah[(size_t)MM * 192];
__device__ __align__(16) __nv_bfloat16 g_Al[(size_t)MM * 192];
__device__ __align__(16) __nv_bfloat16 g_Bp[384 * 576];
__device__ __align__(16) __nv_bfloat16 g_B11[128 * 384];

__device__ __forceinline__ uint32_t smem_u32(const void* p) {
    uint32_t a;
    asm("{ .reg .u64 t; cvta.to.shared.u64 t, %1; cvt.u32.u64 %0, t; }" : "=r"(a) : "l"(p));
    return a;
}
__device__ __forceinline__ void ldsm_x4(uint32_t& r0, uint32_t& r1, uint32_t& r2,
                                        uint32_t& r3, uint32_t addr) {
    asm volatile("ldmatrix.sync.aligned.m8n8.x4.shared.b16 {%0,%1,%2,%3}, [%4];"
                 : "=r"(r0), "=r"(r1), "=r"(r2), "=r"(r3) : "r"(addr));
}
__device__ __forceinline__ void mma16816(float& c0, float& c1, float& c2, float& c3,
                                         uint32_t a0, uint32_t a1, uint32_t a2, uint32_t a3,
                                         uint32_t b0, uint32_t b1) {
    asm volatile("mma.sync.aligned.m16n8k16.row.col.f32.bf16.bf16.f32 "
                 "{%0,%1,%2,%3}, {%4,%5,%6,%7}, {%8,%9}, {%0,%1,%2,%3};"
                 : "+f"(c0), "+f"(c1), "+f"(c2), "+f"(c3)
                 : "r"(a0), "r"(a1), "r"(a2), "r"(a3), "r"(b0), "r"(b1));
}

// ---------------------------------------------------------------------------
// Kernel S: split x into bf16 hi/lo -> g_Ah/g_Al cols [0,128)
// ---------------------------------------------------------------------------
__global__ void k_splitx(const float* __restrict__ x)
{
    int idx = blockIdx.x * 256 + threadIdx.x;     // 0 .. MM*32-1
    int m = idx >> 5, q = (idx & 31) << 2;
    float4 v = *(const float4*)(x + (size_t)m * 128 + q);
    __nv_bfloat16 h[4];
    __nv_bfloat16 l[4];
    float f[4] = {v.x, v.y, v.z, v.w};
#pragma unroll
    for (int i = 0; i < 4; ++i) {
        h[i] = __float2bfloat16(f[i]);
        l[i] = __float2bfloat16(f[i] - __bfloat162float(h[i]));
    }
    *(u64*)(g_Ah + (size_t)m * 192 + q) = *(u64*)h;
    *(u64*)(g_Al + (size_t)m * 192 + q) = *(u64*)l;
}

// ---------------------------------------------------------------------------
// Kernel P1: split W11 -> g_B11 [128,384]: [0,128)=hi, [128,256)=hi, [256,384)=lo
// ---------------------------------------------------------------------------
__global__ void k_prepB11(const float* __restrict__ W11)
{
    int t = blockIdx.x * 256 + threadIdx.x;
    if (t >= 128 * 128) return;
    int n = t >> 7, k = t & 127;
    float w = W11[(size_t)n * 128 + k];
    __nv_bfloat16 hi = __float2bfloat16(w);
    float lo = w - __bfloat162float(hi);
    g_B11[(size_t)n * 384 + k]       = hi;
    g_B11[(size_t)n * 384 + 128 + k] = hi;
    g_B11[(size_t)n * 384 + 256 + k] = __float2bfloat16(lo);
}

// ---------------------------------------------------------------------------
// Kernel P2: fold plane-stress D into W12, split -> g_Bp [384,576]
// ---------------------------------------------------------------------------
__global__ void k_prepB(const float* __restrict__ W12)
{
    int t = blockIdx.x * 256 + threadIdx.x;
    if (t >= 384 * 192) return;
    int n = t / 192, k = t % 192;
    int p3 = (n / 3) * 3, j = n % 3;
    const float C   = 1098.9010989010989f;   // E/(1-nu^2)
    const float CNU = 329.67032967032966f;   // C*nu
    const float CSH = 384.61538461538464f;   // C*(1-nu)/2
    float w;
    if (j == 0)      w = C   * W12[(size_t)p3 * 192 + k] + CNU * W12[(size_t)(p3 + 1) * 192 + k];
    else if (j == 1) w = CNU * W12[(size_t)p3 * 192 + k] + C   * W12[(size_t)(p3 + 1) * 192 + k];
    else             w = CSH * W12[(size_t)n * 192 + k];
    __nv_bfloat16 hi = __float2bfloat16(w);
    float lo = w - __bfloat162float(hi);
    g_Bp[(size_t)n * 576 + k]       = hi;
    g_Bp[(size_t)n * 576 + 192 + k] = hi;
    g_Bp[(size_t)n * 576 + 384 + k] = __float2bfloat16(lo);
}

// ---------------------------------------------------------------------------
// Kernel A: fc11, barrier-free mainloop.
//   grid (512, 2), 512 thr. CTA: M=256, BN=64 (n0 = gy*64). K'=384 = 24 k16.
//   B resident in smem: 64 rows x pitch 784B = 50176B, conflict-free ldsm.
//   A: per-lane b32 LDGs straight into fragments, depth-1 prefetch.
//   Warp grid 8M x 2N -> warp tile 32x32 (acc 16 regs x2 mt).
// ---------------------------------------------------------------------------
#define B11PITCH 784
#define FC11_SMEM 50176

__global__ void __launch_bounds__(512, 1) k_fc11_mma(const float* __restrict__ b11)
{
    extern __shared__ char smem[];
    const uint32_t sb = smem_u32(smem);
    const int tid  = threadIdx.x;
    const int lane = tid & 31;
    const int w    = tid >> 5;          // 0..15
    const int wm   = w >> 1;            // 0..7
    const int wn   = w & 1;
    const int g    = lane >> 2;
    const int t4   = lane & 3;
    const int m0   = blockIdx.x << 8;   // 256 rows per CTA
    const int n0   = blockIdx.y << 6;

    __shared__ float b11s[128];
    if (tid < 128) b11s[tid] = b11[tid];

    // load resident B: 64 rows x 384 bf16 (768B) -> pitch 784
    for (int i = tid; i < 64 * 48; i += 512) {
        int r = i / 48, c = i % 48;
        *(uint4*)(smem + r * B11PITCH + (c << 4)) =
            *(const uint4*)(g_B11 + (size_t)(n0 + r) * 384 + (c << 3));
    }
    __syncthreads();

    float acc[2][4][4];
#pragma unroll
    for (int a = 0; a < 2; ++a)
#pragma unroll
        for (int b = 0; b < 4; ++b)
#pragma unroll
            for (int c = 0; c < 4; ++c) acc[a][b][c] = 0.f;

    const int rowA = m0 + wm * 32 + g;
    const int nb   = ((lane >> 4) << 3) + (lane & 7);
    const int bco  = (lane & 8) << 1;

    auto ldA = [&](int kk, uint32_t a[2][4]) {
        int seg = kk >> 3;                         // 0:hi 1:lo 2:hi
        const __nv_bfloat16* Asrc = (seg == 1) ? g_Al : g_Ah;
        int col = ((kk & 7) << 4) + (t4 << 1);
        const __nv_bfloat16* p = Asrc + (size_t)rowA * 192 + col;
#pragma unroll
        for (int mt = 0; mt < 2; ++mt) {
            const __nv_bfloat16* q = p + mt * 16 * 192;
            a[mt][0] = *(const uint32_t*)q;
            a[mt][1] = *(const uint32_t*)(q + 8 * 192);
            a[mt][2] = *(const uint32_t*)(q + 8);
            a[mt][3] = *(const uint32_t*)(q + 8 * 192 + 8);
        }
    };

    uint32_t acur[2][4], anxt[2][4];
    ldA(0, acur);

#pragma unroll 4
    for (int kk = 0; kk < 24; ++kk) {
        ldA(kk < 23 ? kk + 1 : 23, anxt);
#pragma unroll
        for (int np2 = 0; np2 < 2; ++np2) {
            int n = wn * 32 + np2 * 16 + nb;
            uint32_t b0, b1, b2, b3;
            ldsm_x4(b0, b1, b2, b3, sb + n * B11PITCH + kk * 32 + bco);
#pragma unroll
            for (int mt = 0; mt < 2; ++mt) {
                mma16816(acc[mt][2*np2][0], acc[mt][2*np2][1], acc[mt][2*np2][2], acc[mt][2*np2][3],
                         acur[mt][0], acur[mt][1], acur[mt][2], acur[mt][3], b0, b1);
                mma16816(acc[mt][2*np2+1][0], acc[mt][2*np2+1][1], acc[mt][2*np2+1][2], acc[mt][2*np2+1][3],
                         acur[mt][0], acur[mt][1], acur[mt][2], acur[mt][3], b2, b3);
            }
        }
#pragma unroll
        for (int mt = 0; mt < 2; ++mt)
#pragma unroll
            for (int i = 0; i < 4; ++i) acur[mt][i] = anxt[mt][i];
    }

    // epilogue: fragments hold (even,odd) col pairs -> dnew directly
#pragma unroll
    for (int mt = 0; mt < 2; ++mt)
#pragma unroll
        for (int nn = 0; nn < 4; ++nn) {
            int n = n0 + wn * 32 + nn * 8 + 2 * t4;
            float be = b11s[n], bo = b11s[n + 1];
            int r0 = m0 + wm * 32 + mt * 16 + g;
#pragma unroll
            for (int hh = 0; hh < 2; ++hh) {
                float v0 = acc[mt][nn][2 * hh]     + be;
                float v1 = acc[mt][nn][2 * hh + 1] + bo;
                v0 = v0 > 0.f ? v0 : 0.01f * v0;
                v1 = v1 > 0.f ? v1 : 0.01f * v1;
                float jn = fmaxf(v0, 0.f);
                float delta = sqrtf(jn * jn + v1 * v1 + 1e-12f);
                float dn = __fdividef(0.1f * (delta - 0.01f),
                                      fmaxf(delta, 1e-12f) * 0.09f);
                dn = fminf(fmaxf(dn, 0.f), 1.f);
                g_dnew[(size_t)(r0 + 8 * hh) * 64 + (n >> 1)] = dn;
            }
        }
}

// ---------------------------------------------------------------------------
// Kernel B: prefix-max of dnew over T; writes dmg as bf16 hi/lo into
// g_Ah/g_Al cols [128,192).
// ---------------------------------------------------------------------------
__global__ void k_prefixmax()
{
    int t = blockIdx.x * blockDim.x + threadIdx.x;   // 0..16383
    int b = t >> 6, p = t & 63;
    const float* src = g_dnew + (size_t)b * 512 * 64 + p;
    __nv_bfloat16* dh = g_Ah + (size_t)b * 512 * 192 + 128 + p;
    __nv_bfloat16* dl = g_Al + (size_t)b * 512 * 192 + 128 + p;
    float run = 0.f;
    for (int t0 = 0; t0 < 512; t0 += 8) {
        float v[8];
#pragma unroll
        for (int i = 0; i < 8; ++i) v[i] = src[(size_t)(t0 + i) * 64];
#pragma unroll
        for (int i = 0; i < 8; ++i) {
            run = fmaxf(run, v[i]);
            __nv_bfloat16 hi = __float2bfloat16(run);
            dh[(size_t)(t0 + i) * 192] = hi;
            dl[(size_t)(t0 + i) * 192] = __float2bfloat16(run - __bfloat162float(hi));
        }
    }
}

// ---------------------------------------------------------------------------
// Kernel C: fc12, barrier-free mainloop.
//   grid (512, 4), 512 thr. CTA: M=256, BN=96 (cb = gy*96). K'=576 = 36 k16.
//   B resident in smem: 96 rows x pitch 1168B = 112128B (1 CTA/SM).
//   Warp grid 8M x 2N -> warp tile 32x48, acc[2][6][4].
//   Epilogue: acc -> per-warp slab in (reused) smem -> seq + coalesced stores.
// ---------------------------------------------------------------------------
#define BPITCH 1168
#define FC12_SMEM 112128

__global__ void __launch_bounds__(512, 1) k_fc12_mma()
{
    extern __shared__ char smem[];
    const uint32_t sb = smem_u32(smem);
    const int tid  = threadIdx.x;
    const int lane = tid & 31;
    const int w    = tid >> 5;
    const int wm   = w >> 1;            // 0..7
    const int wn   = w & 1;
    const int g    = lane >> 2;
    const int t4   = lane & 3;
    const int m0   = blockIdx.x << 8;
    const int gy   = blockIdx.y;

    // load resident B: 96 rows x 576 bf16 (1152B) -> pitch 1168
    for (int i = tid; i < 96 * 72; i += 512) {
        int r = i / 72, c = i % 72;
        *(uint4*)(smem + r * BPITCH + (c << 4)) =
            *(const uint4*)(g_Bp + (size_t)(gy * 96 + r) * 576 + (c << 3));
    }
    __syncthreads();

    float acc[2][6][4];
#pragma unroll
    for (int a = 0; a < 2; ++a)
#pragma unroll
        for (int b = 0; b < 6; ++b)
#pragma unroll
            for (int c = 0; c < 4; ++c) acc[a][b][c] = 0.f;

    const int rowA = m0 + wm * 32 + g;
    const int nb   = ((lane >> 4) << 3) + (lane & 7);
    const int bco  = (lane & 8) << 1;

    auto ldA = [&](int kk, uint32_t a[2][4]) {
        int seg = kk / 12;                        // 0:hi 1:lo 2:hi
        const __nv_bfloat16* Asrc = (seg == 1) ? g_Al : g_Ah;
        int col = (kk % 12) * 16 + (t4 << 1);
        const __nv_bfloat16* p = Asrc + (size_t)rowA * 192 + col;
#pragma unroll
        for (int mt = 0; mt < 2; ++mt) {
            const __nv_bfloat16* q = p + mt * 16 * 192;
            a[mt][0] = *(const uint32_t*)q;
            a[mt][1] = *(const uint32_t*)(q + 8 * 192);
            a[mt][2] = *(const uint32_t*)(q + 8);
            a[mt][3] = *(const uint32_t*)(q + 8 * 192 + 8);
        }
    };

    uint32_t acur[2][4], anxt[2][4];
    ldA(0, acur);

#pragma unroll 4
    for (int kk = 0; kk < 36; ++kk) {
        ldA(kk < 35 ? kk + 1 : 35, anxt);
#pragma unroll
        for (int np2 = 0; np2 < 3; ++np2) {
            int n = wn * 48 + np2 * 16 + nb;
            uint32_t b0, b1, b2, b3;
            ldsm_x4(b0, b1, b2, b3, sb + n * BPITCH + kk * 32 + bco);
#pragma unroll
            for (int mt = 0; mt < 2; ++mt) {
                mma16816(acc[mt][2*np2][0], acc[mt][2*np2][1], acc[mt][2*np2][2], acc[mt][2*np2][3],
                         acur[mt][0], acur[mt][1], acur[mt][2], acur[mt][3], b0, b1);
                mma16816(acc[mt][2*np2+1][0], acc[mt][2*np2+1][1], acc[mt][2*np2+1][2], acc[mt][2*np2+1][3],
                         acur[mt][0], acur[mt][1], acur[mt][2], acur[mt][3], b2, b3);
            }
        }
#pragma unroll
        for (int mt = 0; mt < 2; ++mt)
#pragma unroll
            for (int i = 0; i < 4; ++i) acur[mt][i] = anxt[mt][i];
    }

    // ---------------- epilogue (reuse B smem as slabs) ----------------
    __syncthreads();
    float* slab = (float*)smem + w * 1664;     // 32 x 52 floats per warp
#pragma unroll
    for (int mt = 0; mt < 2; ++mt)
#pragma unroll
        for (int nn = 0; nn < 6; ++nn) {
            int row = mt * 16 + g;
            int col = nn * 8 + 2 * t4;
            slab[row * 52 + col]           = acc[mt][nn][0];
            slab[row * 52 + col + 1]       = acc[mt][nn][1];
            slab[(row + 8) * 52 + col]     = acc[mt][nn][2];
            slab[(row + 8) * 52 + col + 1] = acc[mt][nn][3];
        }
    __syncwarp();

    const int mbase = m0 + wm * 32;
    const int cb  = gy * 96 + wn * 48;
    const int pbi = gy * 32 + wn * 16;
#pragma unroll 1
    for (int r = 0; r < 32; ++r) {
        if (lane < 16) {
            float s0 = slab[r * 52 + 3 * lane];
            float s1 = slab[r * 52 + 3 * lane + 1];
            float s2 = slab[r * 52 + 3 * lane + 2];
            float seq = sqrtf(s0 * s0 - s0 * s1 + s1 * s1 + 3.f * s2 * s2 + 1e-12f);
            g_seq[(size_t)(mbase + r) * 128 + pbi + lane] = seq;
        }
        if (lane < 12) {
            float4 v = *(float4*)&slab[r * 52 + 4 * lane];
            *(float4*)&g_strain[(size_t)(mbase + r) * 384 + cb + 4 * lane] = v;
        }
    }
}

// ---------------------------------------------------------------------------
// Kernel E: J2 radial-return ep chains (8-wide load batching for MLP)
// ---------------------------------------------------------------------------
__global__ void k_ep()
{
    int t = blockIdx.x * 256 + threadIdx.x;
    int b = t >> 7, p = t & 127;
    const float* sq = g_seq   + (size_t)b * 512 * 128 + p;
    float*       sc = g_scale + (size_t)b * 512 * 128 + p;
    const float SY = 10.f, H = 100.f;
    const float INV = (float)(1.0 / (3.0 * (1000.0 / 2.6) + 100.0));
    float ep = 0.f;
    for (int t0 = 0; t0 < 512; t0 += 8) {
        float v[8];
#pragma unroll
        for (int i = 0; i < 8; ++i) v[i] = sq[(size_t)(t0 + i) * 128];
        float out[8];
#pragma unroll
        for (int i = 0; i < 8; ++i) {
            float fy = v[i] - fmaf(H, ep, SY);
            if (fy > 0.f) {
                ep = fmaf(fy, INV, ep);
                out[i] = __fdividef(fmaf(H, ep, SY), v[i]);
            } else {
                out[i] = 1.f;
            }
        }
#pragma unroll
        for (int i = 0; i < 8; ++i) sc[(size_t)(t0 + i) * 128] = out[i];
    }
}

// ---------------------------------------------------------------------------
// Kernel F: fc2 + softplus
// ---------------------------------------------------------------------------
__global__ void k_fc2(const float* __restrict__ W2, float* __restrict__ out)
{
    __shared__ float w2s[6 * 384];
    int tid = threadIdx.x;
    for (int i = tid; i < 2304; i += 256) w2s[i] = W2[i];
    __syncthreads();

    int warp = tid >> 5, lane = tid & 31;
    int m = blockIdx.x * 8 + warp;
    const float* sig = g_strain + (size_t)m * 384;
    const float* scl = g_scale  + (size_t)m * 128;
    float acc[6] = {0.f, 0.f, 0.f, 0.f, 0.f, 0.f};
#pragma unroll
    for (int q = 0; q < 4; ++q) {
        int p = lane + 32 * q;
        float s = scl[p];
        float f0 = sig[3 * p], f1 = sig[3 * p + 1], f2 = sig[3 * p + 2];
        float g0 = s * f0, g1 = s * f1, g2 = s * f2;
#pragma unroll
        for (int o = 0; o < 6; ++o) {
            acc[o] = fmaf(g0, w2s[o * 384 + 3 * p],     acc[o]);
            acc[o] = fmaf(g1, w2s[o * 384 + 3 * p + 1], acc[o]);
            acc[o] = fmaf(g2, w2s[o * 384 + 3 * p + 2], acc[o]);
        }
    }
#pragma unroll
    for (int o = 0; o < 6; ++o)
#pragma unroll
        for (int off = 16; off; off >>= 1)
            acc[o] += __shfl_xor_sync(0xffffffffu, acc[o], off);
    if (lane == 0) {
#pragma unroll
        for (int o = 0; o < 6; ++o) {
            float v = acc[o];
            float sp = fmaxf(v, 0.f) + log1pf(expf(-fabsf(v)));
            out[(size_t)m * 6 + o] = sp;
        }
    }
}

// ---------------------------------------------------------------------------
extern "C" void kernel_launch(void* const* d_in, const int* in_sizes, int n_in,
                              void* d_out, int out_size)
{
    const float* x   = (const float*)d_in[0];
    const float* W11 = (const float*)d_in[1];
    const float* b11 = (const float*)d_in[2];
    const float* W12 = (const float*)d_in[3];
    const float* W2  = (const float*)d_in[4];
    float* out = (float*)d_out;

    (void)in_sizes; (void)n_in; (void)out_size;

    cudaFuncSetAttribute(k_fc11_mma, cudaFuncAttributeMaxDynamicSharedMemorySize, FC11_SMEM);
    cudaFuncSetAttribute(k_fc12_mma, cudaFuncAttributeMaxDynamicSharedMemorySize, FC12_SMEM);

    k_splitx<<<MM / 8, 256>>>(x);
    k_prepB11<<<64, 256>>>(W11);
    k_prepB<<<288, 256>>>(W12);
    k_fc11_mma<<<dim3(MM / 256, 2), 512, FC11_SMEM>>>(b11);
    k_prefixmax<<<64, 256>>>();
    k_fc12_mma<<<dim3(MM / 256, 4), 512, FC12_SMEM>>>();
    k_ep<<<128, 256>>>();
    k_fc2<<<MM / 8, 256>>>(W2, out);
}